// round 15
// baseline (speedup 1.0000x reference)
#include <cuda_runtime.h>
#include <cstdint>

#define HW 262144      // 512*512
#define W  512
#define NTILES 8192    // 32 images * 256 tiles

// cos(k*pi/16)
#define C1f 0.98078528040323044913f
#define C2f 0.92387953251128675613f
#define C3f 0.83146961230254523708f
#define C4f 0.70710678118654752440f
#define C5f 0.55557023301960222474f
#define C6f 0.38268343236508977173f
#define C7f 0.19509032201612826785f

__device__ __forceinline__ uint32_t s2u(const void* p) {
    uint32_t a;
    asm("{ .reg .u64 t; cvta.to.shared.u64 t, %1; cvt.u32.u64 %0, t; }"
        : "=r"(a) : "l"(p));
    return a;
}
__device__ __forceinline__ void cp16(uint32_t s, const void* g) {
    asm volatile("cp.async.cg.shared.global [%0], [%1], 16;"
                 :: "r"(s), "l"(g) : "memory");
}
#define CP_COMMIT() asm volatile("cp.async.commit_group;" ::: "memory")
#define CP_WAIT0()  asm volatile("cp.async.wait_group 0;" ::: "memory")

// o[u] = sum_x a[x] * cos((2x+1)u pi/16)
__device__ __forceinline__ void dct8(const float* a, float* o) {
    float s0 = a[0] + a[7], s1 = a[1] + a[6];
    float s2 = a[2] + a[5], s3 = a[3] + a[4];
    float d0 = a[0] - a[7], d1 = a[1] - a[6];
    float d2 = a[2] - a[5], d3 = a[3] - a[4];
    float f0 = s0 + s3, f1 = s1 + s2;
    float e0 = s0 - s3, e1 = s1 - s2;
    o[0] = f0 + f1;
    o[4] = (f0 - f1) * C4f;
    o[2] = fmaf(e0, C2f,  e1 * C6f);
    o[6] = fmaf(e0, C6f, -e1 * C2f);
    o[1] = fmaf(d0, C1f, fmaf(d1,  C3f, fmaf(d2,  C5f,  d3 * C7f)));
    o[3] = fmaf(d0, C3f, fmaf(d1, -C7f, fmaf(d2, -C1f, -d3 * C5f)));
    o[5] = fmaf(d0, C5f, fmaf(d1, -C1f, fmaf(d2,  C7f,  d3 * C3f)));
    o[7] = fmaf(d0, C7f, fmaf(d1, -C5f, fmaf(d2,  C3f, -d3 * C1f)));
}

// o[x] = sum_u a[u] * cos((2x+1)u pi/16)
__device__ __forceinline__ void idct8(const float* a, float* o) {
    float E0 = fmaf(a[2],  C2f, fmaf(a[4],  C4f, fmaf(a[6],  C6f, a[0])));
    float E1 = fmaf(a[2],  C6f, fmaf(a[4], -C4f, fmaf(a[6], -C2f, a[0])));
    float E2 = fmaf(a[2], -C6f, fmaf(a[4], -C4f, fmaf(a[6],  C2f, a[0])));
    float E3 = fmaf(a[2], -C2f, fmaf(a[4],  C4f, fmaf(a[6], -C6f, a[0])));
    float O0 = fmaf(a[1],  C1f, fmaf(a[3],  C3f, fmaf(a[5],  C5f,  a[7] * C7f)));
    float O1 = fmaf(a[1],  C3f, fmaf(a[3], -C7f, fmaf(a[5], -C1f, -a[7] * C5f)));
    float O2 = fmaf(a[1],  C5f, fmaf(a[3], -C1f, fmaf(a[5],  C7f,  a[7] * C3f)));
    float O3 = fmaf(a[1],  C7f, fmaf(a[3], -C5f, fmaf(a[5],  C3f, -a[7] * C1f)));
    o[0] = E0 + O0;  o[7] = E0 - O0;
    o[1] = E1 + O1;  o[6] = E1 - O1;
    o[2] = E2 + O2;  o[5] = E2 - O2;
    o[3] = E3 + O3;  o[4] = E3 - O3;
}

__global__ __launch_bounds__(256)
void diffjpeg_kernel(const float* __restrict__ img,
                     const float* __restrict__ ytab,
                     const float* __restrict__ ctab,
                     float* __restrict__ out)
{
    // pixel planes (16B-aligned rows, conflict-free)
    __shared__ float sY [32 * 36];     // stride 36
    __shared__ float sCb[16 * 20];     // stride 20
    __shared__ float sCr[16 * 20];
    // transpose scratch; also reused as the chroma-pooling exchange buffer
    __shared__ float sT [24 * 104];
    // quant tables: [2i]=0.25*aa/(0.4*tab), [2i+1]=0.25*aa*0.4*tab
    __shared__ float sRS[2][128];
    // cp.async staging: per-thread float4 per plane (owner-read-only)
    __shared__ float sPre[3][1024];

    const int tid = threadIdx.x;
    const int ty  = tid >> 3;             // 0..31
    const int txq = tid & 7;              // 0..7 (x in float4 units)
    const int stride = gridDim.x;

    const uint32_t pa0 = s2u(&sPre[0][tid * 4]);
    const uint32_t pa1 = s2u(&sPre[1][tid * 4]);
    const uint32_t pa2 = s2u(&sPre[2][tid * 4]);

    // prologue: prefetch first tile (register-free)
    int tile = blockIdx.x;
    {
        const int t0 = tile & 255;
        const float* p0 = img + (size_t)(tile >> 8) * 3 * HW
                        + ((t0 >> 4) * 32 + ty) * W + (t0 & 15) * 32 + txq * 4;
        cp16(pa0, p0);
        cp16(pa1, p0 + HW);
        cp16(pa2, p0 + 2 * HW);
        CP_COMMIT();
    }

    // quant-table init ONCE per CTA (warps 6,7; idle during transforms)
    if (tid >= 192) {
        #pragma unroll
        for (int k = 0; k < 2; k++) {
            int idx = (tid - 192) + 64 * k;      // 0..127
            int ti = idx >> 6, i = idx & 63;
            int u = i >> 3, v = i & 7;
            float aa = (u ? 1.0f : C4f) * (v ? 1.0f : C4f);
            float tq = (ti ? ctab[i] : ytab[i]) * 0.4f;
            sRS[ti][2 * i]     = 0.25f * aa / tq;
            sRS[ti][2 * i + 1] = 0.25f * aa * tq;
        }
    }

    // per-thread transform-role constants (loop-invariant)
    float* plane = sY;
    int poff = 0, ti = 0;
    const int blk = tid >> 3, r = tid & 7;
    const bool act = (tid < 192);
    if (act) {
        if (blk < 16) {
            plane = sY;  poff = ((blk >> 2) * 8 + r) * 36 + (blk & 3) * 8;  ti = 0;
        } else {
            int b = blk & 3;
            plane = (blk < 20) ? sCb : sCr;
            poff = (((b >> 1) * 8 + r) * 20) + (b & 1) * 8;  ti = 1;
        }
    }
    float* const trow = &sT[blk * 104 + r * 12];
    float* const tcol = &sT[blk * 104 + r];

    // back-end constants (/255 folded; clip in [0,1])
    const float KI  = 1.0f / 255.0f;
    const float KO  = 128.0f / 255.0f;
    const float KCr = 1.402f / 255.0f;
    const float KG1 = -0.344136f / 255.0f;
    const float KG2 = -0.714136f / 255.0f;
    const float KCb = 1.772f / 255.0f;

    for (;;) {
        const int bimg = tile >> 8;
        const int t    = tile & 255;
        const int grow = (t >> 4) * 32 + ty;
        const int gcol = (t & 15) * 32 + txq * 4;
        float* q = out + (size_t)bimg * 3 * HW + grow * W + gcol;

        // ---------- front end: staged RGB -> YCbCr + chroma pool ----------
        CP_WAIT0();                      // own slot only: no barrier needed
        float4 r4 = *(const float4*)&sPre[0][tid * 4];
        float4 g4 = *(const float4*)&sPre[1][tid * 4];
        float4 b4 = *(const float4*)&sPre[2][tid * 4];

        float rr[4] = {r4.x, r4.y, r4.z, r4.w};
        float gg[4] = {g4.x, g4.y, g4.z, g4.w};
        float bb[4] = {b4.x, b4.y, b4.z, b4.w};

        float yv[4], cbv[4], crv[4];
        #pragma unroll
        for (int j = 0; j < 4; j++) {
            yv [j] = fmaf(rr[j],  76.245f,   fmaf(gg[j],  149.685f,  fmaf(bb[j],  29.07f,    -128.0f)));
            cbv[j] = fmaf(rr[j], -43.02768f, fmaf(gg[j], -84.47232f,       bb[j] * 127.5f));
            crv[j] = fmaf(rr[j], 127.5f,     fmaf(gg[j], -106.76544f,     bb[j] * -20.73456f));
        }

        // staged values consumed -> safe to refill the same slots (register-free)
        const int ntile = tile + stride;
        const bool more = (ntile < NTILES);
        if (more) {
            const int nt = ntile & 255;
            const float* np = img + (size_t)(ntile >> 8) * 3 * HW
                            + ((nt >> 4) * 32 + ty) * W + (nt & 15) * 32 + txq * 4;
            cp16(pa0, np);
            cp16(pa1, np + HW);
            cp16(pa2, np + 2 * HW);
        }
        CP_COMMIT();

        *(float4*)&sY[ty * 36 + txq * 4] = make_float4(yv[0], yv[1], yv[2], yv[3]);

        float cb0 = cbv[0] + cbv[1], cb1 = cbv[2] + cbv[3];
        float cr0 = crv[0] + crv[1], cr1 = crv[2] + crv[3];
        if (ty & 1)
            *(float4*)&sT[tid * 4] = make_float4(cb0, cb1, cr0, cr1);
        __syncwarp();
        if (!(ty & 1)) {
            float4 prt = *(const float4*)&sT[(tid ^ 8) * 4];
            int ci = (ty >> 1) * 20 + txq * 2;
            *(float2*)&sCb[ci] = make_float2(0.25f * (cb0 + prt.x), 0.25f * (cb1 + prt.y));
            *(float2*)&sCr[ci] = make_float2(0.25f * (cr0 + prt.z), 0.25f * (cr1 + prt.w));
        }
        __syncthreads();

        // ---------- transforms: groups warp-local (warps 0-5) ----------
        if (act) {
            float a[8], o[8];
            float4 v0 = *(const float4*)&plane[poff];
            float4 v1 = *(const float4*)&plane[poff + 4];
            a[0] = v0.x; a[1] = v0.y; a[2] = v0.z; a[3] = v0.w;
            a[4] = v1.x; a[5] = v1.y; a[6] = v1.z; a[7] = v1.w;
            dct8(a, o);
            *(float4*)&trow[0] = make_float4(o[0], o[1], o[2], o[3]);
            *(float4*)&trow[4] = make_float4(o[4], o[5], o[6], o[7]);
            __syncwarp();

            #pragma unroll
            for (int x = 0; x < 8; x++) a[x] = tcol[12 * x];
            dct8(a, o);
            const float* pT = &sRS[ti][2 * r];
            #pragma unroll
            for (int u = 0; u < 8; u++) {
                float2 rs = *(const float2*)&pT[16 * u];
                float tq = o[u] * rs.x;
                float rq = rintf(tq);            // round-half-even == jnp.round
                float dq = tq - rq;
                a[u] = fmaf(dq * dq, dq, rq) * rs.y;
            }
            idct8(a, o);
            #pragma unroll
            for (int x = 0; x < 8; x++) tcol[12 * x] = o[x];
            __syncwarp();

            float4 w0 = *(const float4*)&trow[0];
            float4 w1 = *(const float4*)&trow[4];
            a[0] = w0.x; a[1] = w0.y; a[2] = w0.z; a[3] = w0.w;
            a[4] = w1.x; a[5] = w1.y; a[6] = w1.z; a[7] = w1.w;
            idct8(a, o);
            *(float4*)&plane[poff]     = make_float4(o[0], o[1], o[2], o[3]);
            *(float4*)&plane[poff + 4] = make_float4(o[4], o[5], o[6], o[7]);
        }
        __syncthreads();

        // ---------- back end: upsample, YCbCr->RGB, clip, store ----------
        float4 yq = *(const float4*)&sY[ty * 36 + txq * 4];
        const int ci = (ty >> 1) * 20 + txq * 2;
        float2 cbl = *(const float2*)&sCb[ci];
        float2 crl = *(const float2*)&sCr[ci];

        float yb[4]  = {fmaf(yq.x, KI, KO), fmaf(yq.y, KI, KO),
                        fmaf(yq.z, KI, KO), fmaf(yq.w, KI, KO)};
        float cbp[4] = {cbl.x, cbl.x, cbl.y, cbl.y};
        float crp[4] = {crl.x, crl.x, crl.y, crl.y};

        float4 orv, ogv, obv;
        float* po_r = &orv.x;
        float* po_g = &ogv.x;
        float* po_b = &obv.x;
        #pragma unroll
        for (int j = 0; j < 4; j++) {
            float ro = fmaf(crp[j], KCr, yb[j]);
            float go = fmaf(crp[j], KG2, fmaf(cbp[j], KG1, yb[j]));
            float bo = fmaf(cbp[j], KCb, yb[j]);
            po_r[j] = fminf(fmaxf(ro, 0.0f), 1.0f);
            po_g[j] = fminf(fmaxf(go, 0.0f), 1.0f);
            po_b[j] = fminf(fmaxf(bo, 0.0f), 1.0f);
        }
        __stcs((float4*)q,            orv);
        __stcs((float4*)(q + HW),     ogv);
        __stcs((float4*)(q + 2 * HW), obv);

        if (!more) break;
        tile = ntile;
        __syncthreads();   // back-end plane reads done before next front-end writes
    }
}

extern "C" void kernel_launch(void* const* d_in, const int* in_sizes, int n_in,
                              void* d_out, int out_size)
{
    const float* img  = (const float*)d_in[0];
    const float* ytab = (const float*)d_in[1];
    const float* ctab = (const float*)d_in[2];
    float* out = (float*)d_out;

    // persistent single wave: 152 SMs * 7 CTAs (smem-limited occupancy)
    diffjpeg_kernel<<<1064, 256>>>(img, ytab, ctab, out);
}

// round 16
// speedup vs baseline: 1.1164x; 1.1164x over previous
#include <cuda_runtime.h>

#define HW 262144      // 512*512
#define W  512

// cos(k*pi/16)
#define C1f 0.98078528040323044913f
#define C2f 0.92387953251128675613f
#define C3f 0.83146961230254523708f
#define C4f 0.70710678118654752440f
#define C5f 0.55557023301960222474f
#define C6f 0.38268343236508977173f
#define C7f 0.19509032201612826785f

// o[u] = sum_x a[x] * cos((2x+1)u pi/16)
__device__ __forceinline__ void dct8(const float* a, float* o) {
    float s0 = a[0] + a[7], s1 = a[1] + a[6];
    float s2 = a[2] + a[5], s3 = a[3] + a[4];
    float d0 = a[0] - a[7], d1 = a[1] - a[6];
    float d2 = a[2] - a[5], d3 = a[3] - a[4];
    float f0 = s0 + s3, f1 = s1 + s2;
    float e0 = s0 - s3, e1 = s1 - s2;
    o[0] = f0 + f1;
    o[4] = (f0 - f1) * C4f;
    o[2] = fmaf(e0, C2f,  e1 * C6f);
    o[6] = fmaf(e0, C6f, -e1 * C2f);
    o[1] = fmaf(d0, C1f, fmaf(d1,  C3f, fmaf(d2,  C5f,  d3 * C7f)));
    o[3] = fmaf(d0, C3f, fmaf(d1, -C7f, fmaf(d2, -C1f, -d3 * C5f)));
    o[5] = fmaf(d0, C5f, fmaf(d1, -C1f, fmaf(d2,  C7f,  d3 * C3f)));
    o[7] = fmaf(d0, C7f, fmaf(d1, -C5f, fmaf(d2,  C3f, -d3 * C1f)));
}

// o[x] = sum_u a[u] * cos((2x+1)u pi/16)
__device__ __forceinline__ void idct8(const float* a, float* o) {
    float E0 = fmaf(a[2],  C2f, fmaf(a[4],  C4f, fmaf(a[6],  C6f, a[0])));
    float E1 = fmaf(a[2],  C6f, fmaf(a[4], -C4f, fmaf(a[6], -C2f, a[0])));
    float E2 = fmaf(a[2], -C6f, fmaf(a[4], -C4f, fmaf(a[6],  C2f, a[0])));
    float E3 = fmaf(a[2], -C2f, fmaf(a[4],  C4f, fmaf(a[6], -C6f, a[0])));
    float O0 = fmaf(a[1],  C1f, fmaf(a[3],  C3f, fmaf(a[5],  C5f,  a[7] * C7f)));
    float O1 = fmaf(a[1],  C3f, fmaf(a[3], -C7f, fmaf(a[5], -C1f, -a[7] * C5f)));
    float O2 = fmaf(a[1],  C5f, fmaf(a[3], -C1f, fmaf(a[5],  C7f,  a[7] * C3f)));
    float O3 = fmaf(a[1],  C7f, fmaf(a[3], -C5f, fmaf(a[5],  C3f, -a[7] * C1f)));
    o[0] = E0 + O0;  o[7] = E0 - O0;
    o[1] = E1 + O1;  o[6] = E1 - O1;
    o[2] = E2 + O2;  o[5] = E2 - O2;
    o[3] = E3 + O3;  o[4] = E3 - O3;
}

__global__ __launch_bounds__(256)
void diffjpeg_kernel(const float* __restrict__ img,
                     const float* __restrict__ ytab,
                     const float* __restrict__ ctab,
                     float* __restrict__ out)
{
    // pixel planes: strides multiple of 4 (16B-aligned rows) AND conflict-free
    __shared__ float sY [32 * 36];     // stride 36
    __shared__ float sCb[16 * 20];     // stride 20
    __shared__ float sCr[16 * 20];
    // transpose scratch: 24 groups, row stride 12 (16B-aligned), group stride 104.
    // Also reused (pre-transform) as the chroma-pooling exchange buffer.
    __shared__ float sT [24 * 104];
    // interleaved quant tables: [2i] = 0.25*aa/(0.4*tab), [2i+1] = 0.25*aa*0.4*tab
    __shared__ float sRS[2][128];

    const int tid = threadIdx.x;

    // quant-table init on warps 6,7 (idle during transform phase)
    if (tid >= 192) {
        #pragma unroll
        for (int k = 0; k < 2; k++) {
            int idx = (tid - 192) + 64 * k;      // 0..127
            int ti = idx >> 6, i = idx & 63;
            int u = i >> 3, v = i & 7;
            float aa = (u ? 1.0f : C4f) * (v ? 1.0f : C4f);
            float tq = (ti ? ctab[i] : ytab[i]) * 0.4f;
            sRS[ti][2 * i]     = 0.25f * aa / tq;
            sRS[ti][2 * i + 1] = 0.25f * aa * tq;
        }
    }

    // ---------------- front end: load RGB, YCbCr, 2x2 chroma pool ----------
    const int tile = blockIdx.x;
    const int bimg = tile >> 8;            // 256 tiles per image
    const int t    = tile & 255;
    const int ty   = tid >> 3;             // 0..31
    const int txq  = tid & 7;              // 0..7 (x in float4 units)
    const int grow = (t >> 4) * 32 + ty;
    const int gcol = (t & 15) * 32 + txq * 4;

    const float* p = img + (size_t)bimg * 3 * HW + grow * W + gcol;
    float4 r4 = __ldcs((const float4*)p);
    float4 g4 = __ldcs((const float4*)(p + HW));
    float4 b4 = __ldcs((const float4*)(p + 2 * HW));

    float rr[4] = {r4.x, r4.y, r4.z, r4.w};
    float gg[4] = {g4.x, g4.y, g4.z, g4.w};
    float bb[4] = {b4.x, b4.y, b4.z, b4.w};

    float yv[4], cbv[4], crv[4];
    #pragma unroll
    for (int j = 0; j < 4; j++) {
        // coefficients pre-multiplied by 255; Y centered (-128)
        yv [j] = fmaf(rr[j],  76.245f,   fmaf(gg[j],  149.685f,  fmaf(bb[j],  29.07f,    -128.0f)));
        cbv[j] = fmaf(rr[j], -43.02768f, fmaf(gg[j], -84.47232f,       bb[j] * 127.5f));
        crv[j] = fmaf(rr[j], 127.5f,     fmaf(gg[j], -106.76544f,     bb[j] * -20.73456f));
    }

    *(float4*)&sY[ty * 36 + txq * 4] = make_float4(yv[0], yv[1], yv[2], yv[3]);

    // horizontal pair sums in-thread; vertical partner (row ty^1 = tid^8)
    // exchanged through the (still idle) sT scratch. Store unconditionally
    // (own slot, conflict-free); only even rows consume partner slots.
    float cb0 = cbv[0] + cbv[1], cb1 = cbv[2] + cbv[3];
    float cr0 = crv[0] + crv[1], cr1 = crv[2] + crv[3];
    *(float4*)&sT[tid * 4] = make_float4(cb0, cb1, cr0, cr1);
    __syncwarp();
    if (!(ty & 1)) {
        float4 prt = *(const float4*)&sT[(tid ^ 8) * 4];
        int ci = (ty >> 1) * 20 + txq * 2;
        *(float2*)&sCb[ci] = make_float2(0.25f * (cb0 + prt.x), 0.25f * (cb1 + prt.y));
        *(float2*)&sCr[ci] = make_float2(0.25f * (cr0 + prt.z), 0.25f * (cr1 + prt.w));
    }
    __syncthreads();

    // ---------------- transforms: groups warp-local ------------------------
    // blk = tid>>3: groups 0..23 live on warps 0..5 (4 groups per warp).
    // 0..15 = Y blocks (4x4), 16..19 = Cb, 20..23 = Cr. Warps 6,7 idle here.
    float* plane = sY;
    int poff = 0, ti = 0;
    const int blk = tid >> 3, r = tid & 7;
    const bool act = (tid < 192);
    if (act) {
        if (blk < 16) {
            plane = sY;  poff = ((blk >> 2) * 8 + r) * 36 + (blk & 3) * 8;  ti = 0;
        } else {
            int b = blk & 3;
            plane = (blk < 20) ? sCb : sCr;
            poff = (((b >> 1) * 8 + r) * 20) + (b & 1) * 8;  ti = 1;
        }
    }
    float* const trow = &sT[blk * 104 + r * 12];   // 16B-aligned row base
    float* const tcol = &sT[blk * 104 + r];        // column base, v = r

    float a[8], o[8];

    if (act) {
        // stage 1: row DCT, vector plane read, vector row write
        float4 v0 = *(const float4*)&plane[poff];
        float4 v1 = *(const float4*)&plane[poff + 4];
        a[0] = v0.x; a[1] = v0.y; a[2] = v0.z; a[3] = v0.w;
        a[4] = v1.x; a[5] = v1.y; a[6] = v1.z; a[7] = v1.w;
        dct8(a, o);
        *(float4*)&trow[0] = make_float4(o[0], o[1], o[2], o[3]);
        *(float4*)&trow[4] = make_float4(o[4], o[5], o[6], o[7]);
        __syncwarp();      // groups are warp-local

        // stage 2+3: column DCT, quant/dequant (diff_round), column IDCT
        #pragma unroll
        for (int x = 0; x < 8; x++) a[x] = tcol[12 * x];
        dct8(a, o);
        const float* pT = &sRS[ti][2 * r];
        #pragma unroll
        for (int u = 0; u < 8; u++) {
            float2 rs = *(const float2*)&pT[16 * u];
            float tq = o[u] * rs.x;
            float rq = rintf(tq);            // round-half-even == jnp.round
            float dq = tq - rq;
            a[u] = fmaf(dq * dq, dq, rq) * rs.y;
        }
        idct8(a, o);                          // o[x] = recon column v
        #pragma unroll
        for (int x = 0; x < 8; x++) tcol[12 * x] = o[x];
        __syncwarp();

        // stage 4: row IDCT, vector row read, vector plane write (centered)
        float4 w0 = *(const float4*)&trow[0];
        float4 w1 = *(const float4*)&trow[4];
        a[0] = w0.x; a[1] = w0.y; a[2] = w0.z; a[3] = w0.w;
        a[4] = w1.x; a[5] = w1.y; a[6] = w1.z; a[7] = w1.w;
        idct8(a, o);
        *(float4*)&plane[poff]     = make_float4(o[0], o[1], o[2], o[3]);
        *(float4*)&plane[poff + 4] = make_float4(o[4], o[5], o[6], o[7]);
    }
    __syncthreads();

    // ---------------- back end: upsample, YCbCr->RGB, clip, store ----------
    // /255 folded into coefficients; clip in [0,1].
    const float KI  = 1.0f / 255.0f;           // y scale
    const float KO  = 128.0f / 255.0f;         // +128 then /255
    const float KCr = 1.402f / 255.0f;
    const float KG1 = -0.344136f / 255.0f;
    const float KG2 = -0.714136f / 255.0f;
    const float KCb = 1.772f / 255.0f;

    float4 yq = *(const float4*)&sY[ty * 36 + txq * 4];
    const int ci = (ty >> 1) * 20 + txq * 2;
    float2 cbl = *(const float2*)&sCb[ci];
    float2 crl = *(const float2*)&sCr[ci];

    float yb[4]  = {fmaf(yq.x, KI, KO), fmaf(yq.y, KI, KO),
                    fmaf(yq.z, KI, KO), fmaf(yq.w, KI, KO)};
    float cbp[4] = {cbl.x, cbl.x, cbl.y, cbl.y};
    float crp[4] = {crl.x, crl.x, crl.y, crl.y};

    float4 orv, ogv, obv;
    float* po_r = &orv.x;
    float* po_g = &ogv.x;
    float* po_b = &obv.x;
    #pragma unroll
    for (int j = 0; j < 4; j++) {
        float ro = fmaf(crp[j], KCr, yb[j]);
        float go = fmaf(crp[j], KG2, fmaf(cbp[j], KG1, yb[j]));
        float bo = fmaf(cbp[j], KCb, yb[j]);
        po_r[j] = fminf(fmaxf(ro, 0.0f), 1.0f);
        po_g[j] = fminf(fmaxf(go, 0.0f), 1.0f);
        po_b[j] = fminf(fmaxf(bo, 0.0f), 1.0f);
    }
    float* q = out + (size_t)bimg * 3 * HW + grow * W + gcol;
    __stcs((float4*)q,            orv);
    __stcs((float4*)(q + HW),     ogv);
    __stcs((float4*)(q + 2 * HW), obv);
}

extern "C" void kernel_launch(void* const* d_in, const int* in_sizes, int n_in,
                              void* d_out, int out_size)
{
    const float* img  = (const float*)d_in[0];
    const float* ytab = (const float*)d_in[1];
    const float* ctab = (const float*)d_in[2];
    float* out = (float*)d_out;

    // 32 images * (512/32)^2 tiles = 8192 CTAs
    diffjpeg_kernel<<<8192, 256>>>(img, ytab, ctab, out);
}